// round 2
// baseline (speedup 1.0000x reference)
#include <cuda_runtime.h>
#include <math.h>

// ---------------------------------------------------------------------------
// DANet head, fp32 SIMT baseline.
// Shapes: B=4, Cin=2048, H=W=64 (N=4096 px/batch), Ci=512, Cq=64, Cout=19.
// ---------------------------------------------------------------------------

#define BATCH 4
#define NPIX  4096
#define COUT  512

// ------------------------- scratch (device globals) ------------------------
__device__ float g_wt5a[9u * 2048u * 512u];        // [tap][ci][co]
__device__ float g_wt5c[9u * 2048u * 512u];
__device__ float g_wt51[9u * 512u * 512u];
__device__ float g_wt52[9u * 512u * 512u];
__device__ float g_wqT[512 * 64];                  // [ci][co]
__device__ float g_wkT[512 * 64];
__device__ float g_wvT[512 * 512];
__device__ float g_w8T[512 * 19];
__device__ float g_feat1[(size_t)BATCH * 512 * 4096];
__device__ float g_feat2[(size_t)BATCH * 512 * 4096];
__device__ float g_q[(size_t)BATCH * 64 * 4096];
__device__ float g_k[(size_t)BATCH * 64 * 4096];
__device__ float g_vT[(size_t)BATCH * 4096 * 512]; // [n][c]
__device__ float g_G[(size_t)BATCH * 4096 * 4096]; // energy^T, then row-softmaxed
__device__ float g_sa[(size_t)BATCH * 512 * 4096];
__device__ float g_sc[(size_t)BATCH * 512 * 4096];
__device__ float g_saconv[(size_t)BATCH * 512 * 4096];
__device__ float g_fsum[(size_t)BATCH * 512 * 4096];
__device__ float g_fT[(size_t)BATCH * 4096 * 512]; // feat2 transposed per batch
__device__ float g_camE[(size_t)BATCH * 512 * 512];
__device__ float g_camA[(size_t)BATCH * 512 * 512]; // attn^T  [d][c]

// ------------------------- weight re-layout kernels ------------------------
// W[co][ci][3x3] -> Wt[tap][ci][co]   (Cout = 512)
__global__ void wtrans3x3(const float* __restrict__ W, float* __restrict__ Wt, int Cin)
{
    long long n = (long long)512 * Cin * 9;
    long long cs = (long long)Cin * 512;
    for (long long i = (long long)blockIdx.x * blockDim.x + threadIdx.x; i < n;
         i += (long long)gridDim.x * blockDim.x) {
        int tap = (int)(i / cs);
        long long r = i - (long long)tap * cs;
        int ci = (int)(r / 512);
        int co = (int)(r - (long long)ci * 512);
        Wt[i] = W[((long long)co * Cin + ci) * 9 + tap];
    }
}

// W[co][ci] -> Wt[ci][co]
__global__ void wtrans1x1(const float* __restrict__ W, float* __restrict__ Wt,
                          int Cin, int Cout)
{
    int i = blockIdx.x * blockDim.x + threadIdx.x;
    if (i < Cin * Cout) {
        int ci = i / Cout, co = i - ci * Cout;
        Wt[i] = W[co * Cin + ci];
    }
}

// ------------------------- 3x3 conv + BN + ReLU (+res) ---------------------
// Y[b,co,p] = relu(bn(sum_{tap,ci} Wt[tap][ci][co] * X[b,ci,shift(p,tap)])) (+ res)
__global__ void __launch_bounds__(256, 2)
conv3x3_kernel(const float* __restrict__ X, const float* __restrict__ Wt, int Cin,
               const float* __restrict__ bns, const float* __restrict__ bnb,
               const float* __restrict__ bnm, const float* __restrict__ bnv,
               const float* __restrict__ res, float* __restrict__ Y)
{
    __shared__ float As[16][128];
    __shared__ float Bs[16][128];

    const int p0  = blockIdx.x * 128;
    const int co0 = blockIdx.y * 128;
    const int b   = blockIdx.z;
    const float* Xb = X + (size_t)b * Cin * NPIX;

    const int tid = threadIdx.x;
    const int ty = tid >> 4, tx = tid & 15;

    float acc[8][8];
#pragma unroll
    for (int i = 0; i < 8; i++)
#pragma unroll
        for (int j = 0; j < 8; j++) acc[i][j] = 0.f;

    // per-thread fixed load slots
    int aofs[8];
#pragma unroll
    for (int s = 0; s < 8; s++) {
        int idx = tid + s * 256;
        int kk = idx >> 7, e = idx & 127;
        aofs[s] = kk * COUT + co0 + e;
    }

    for (int tap = 0; tap < 9; tap++) {
        const int dy = tap / 3 - 1, dx = tap % 3 - 1;
        const float* Wtap = Wt + (size_t)tap * Cin * COUT;

        int bofs[8];
#pragma unroll
        for (int s = 0; s < 8; s++) {
            int idx = tid + s * 256;
            int kk = idx >> 7, e = idx & 127;
            int p = p0 + e;
            int yy = (p >> 6) + dy, xx = (p & 63) + dx;
            bool ok = ((unsigned)yy < 64u) && ((unsigned)xx < 64u);
            bofs[s] = ok ? (kk * NPIX + (yy << 6) + xx) : -1;
        }

        for (int c0 = 0; c0 < Cin; c0 += 16) {
            const float* Wc = Wtap + (size_t)c0 * COUT;
            const float* Xc = Xb + (size_t)c0 * NPIX;
#pragma unroll
            for (int s = 0; s < 8; s++) {
                int idx = tid + s * 256;
                int kk = idx >> 7, e = idx & 127;
                As[kk][e] = Wc[aofs[s]];
                Bs[kk][e] = (bofs[s] >= 0) ? Xc[bofs[s]] : 0.f;
            }
            __syncthreads();
#pragma unroll
            for (int kk = 0; kk < 16; kk++) {
                float4 a0 = *(const float4*)&As[kk][ty * 8];
                float4 a1 = *(const float4*)&As[kk][ty * 8 + 4];
                float4 b0 = *(const float4*)&Bs[kk][tx * 8];
                float4 b1 = *(const float4*)&Bs[kk][tx * 8 + 4];
                float a[8] = {a0.x, a0.y, a0.z, a0.w, a1.x, a1.y, a1.z, a1.w};
                float bb[8] = {b0.x, b0.y, b0.z, b0.w, b1.x, b1.y, b1.z, b1.w};
#pragma unroll
                for (int i = 0; i < 8; i++)
#pragma unroll
                    for (int j = 0; j < 8; j++)
                        acc[i][j] = fmaf(a[i], bb[j], acc[i][j]);
            }
            __syncthreads();
        }
    }

#pragma unroll
    for (int i = 0; i < 8; i++) {
        int gi = co0 + ty * 8 + i;
        float sc = bns[gi] * rsqrtf(bnv[gi] + 1e-5f);
        float sh = bnb[gi] - sc * bnm[gi];
#pragma unroll
        for (int j = 0; j < 8; j++) {
            int gj = p0 + tx * 8 + j;
            float v = fmaxf(fmaf(sc, acc[i][j], sh), 0.f);
            size_t o = ((size_t)b * COUT + gi) * NPIX + gj;
            if (res) v += res[o];
            Y[o] = v;
        }
    }
}

// ------------------------- generic TN GEMM ---------------------------------
// C[i,j] = sum_k A[k*lda+i] * B[k*ldb+j]   (per blockIdx.z batch, strides s*)
// epi: 0 store | 1 +bias[i] | 2 gamma*acc + res[i*ldc+j] | 3 transposed store CT[j*ldc+i]+bias[i]
__global__ void __launch_bounds__(256, 2)
gemm_tn_kernel(const float* __restrict__ A, long long sA, int lda,
               const float* __restrict__ B, long long sB, int ldb,
               float* __restrict__ C, long long sC, int ldc,
               int M, int K, int epi,
               const float* __restrict__ bias,
               const float* __restrict__ res, long long sRes,
               const float* __restrict__ gammaPtr)
{
    __shared__ float As[16][128];
    __shared__ float Bs[16][128];

    const int bj = blockIdx.x * 128;
    const int bi = blockIdx.y * 128;
    const int z = blockIdx.z;
    A += (long long)z * sA;
    B += (long long)z * sB;
    C += (long long)z * sC;

    const int tid = threadIdx.x;
    const int ty = tid >> 4, tx = tid & 15;

    float acc[8][8];
#pragma unroll
    for (int i = 0; i < 8; i++)
#pragma unroll
        for (int j = 0; j < 8; j++) acc[i][j] = 0.f;

    for (int k0 = 0; k0 < K; k0 += 16) {
#pragma unroll
        for (int s = 0; s < 8; s++) {
            int idx = tid + s * 256;
            int kk = idx >> 7, e = idx & 127;
            int gi = bi + e;
            As[kk][e] = (gi < M) ? A[(long long)(k0 + kk) * lda + gi] : 0.f;
            Bs[kk][e] = B[(long long)(k0 + kk) * ldb + bj + e];
        }
        __syncthreads();
#pragma unroll
        for (int kk = 0; kk < 16; kk++) {
            float4 a0 = *(const float4*)&As[kk][ty * 8];
            float4 a1 = *(const float4*)&As[kk][ty * 8 + 4];
            float4 b0 = *(const float4*)&Bs[kk][tx * 8];
            float4 b1 = *(const float4*)&Bs[kk][tx * 8 + 4];
            float a[8] = {a0.x, a0.y, a0.z, a0.w, a1.x, a1.y, a1.z, a1.w};
            float bb[8] = {b0.x, b0.y, b0.z, b0.w, b1.x, b1.y, b1.z, b1.w};
#pragma unroll
            for (int i = 0; i < 8; i++)
#pragma unroll
                for (int j = 0; j < 8; j++)
                    acc[i][j] = fmaf(a[i], bb[j], acc[i][j]);
        }
        __syncthreads();
    }

    float gamma = (epi == 2) ? *gammaPtr : 1.f;
    const float* rz = (epi == 2) ? (res + (long long)z * sRes) : nullptr;

#pragma unroll
    for (int i = 0; i < 8; i++) {
        int gi = bi + ty * 8 + i;
        if (gi >= M) continue;
#pragma unroll
        for (int j = 0; j < 8; j++) {
            int gj = bj + tx * 8 + j;
            float v = acc[i][j];
            if (epi == 1) {
                C[(long long)gi * ldc + gj] = v + bias[gi];
            } else if (epi == 2) {
                C[(long long)gi * ldc + gj] = fmaf(gamma, v, rz[(long long)gi * ldc + gj]);
            } else if (epi == 3) {
                C[(long long)gj * ldc + gi] = v + bias[gi];
            } else {
                C[(long long)gi * ldc + gj] = v;
            }
        }
    }
}

// ------------------------- PAM row softmax (rows of 4096, in-place) --------
__global__ void softmax_rows4096(float* __restrict__ G)
{
    long long row = blockIdx.x;
    float* r = G + row * 4096;
    int t = threadIdx.x;

    float4 v[4];
    float mx = -INFINITY;
#pragma unroll
    for (int s = 0; s < 4; s++) {
        v[s] = ((const float4*)r)[t + s * 256];
        mx = fmaxf(mx, fmaxf(fmaxf(v[s].x, v[s].y), fmaxf(v[s].z, v[s].w)));
    }
    __shared__ float red[256];
    red[t] = mx; __syncthreads();
    for (int o = 128; o > 0; o >>= 1) {
        if (t < o) red[t] = fmaxf(red[t], red[t + o]);
        __syncthreads();
    }
    mx = red[0]; __syncthreads();

    float sum = 0.f;
#pragma unroll
    for (int s = 0; s < 4; s++) {
        v[s].x = __expf(v[s].x - mx);
        v[s].y = __expf(v[s].y - mx);
        v[s].z = __expf(v[s].z - mx);
        v[s].w = __expf(v[s].w - mx);
        sum += v[s].x + v[s].y + v[s].z + v[s].w;
    }
    red[t] = sum; __syncthreads();
    for (int o = 128; o > 0; o >>= 1) {
        if (t < o) red[t] += red[t + o];
        __syncthreads();
    }
    float inv = 1.f / red[0];
#pragma unroll
    for (int s = 0; s < 4; s++) {
        v[s].x *= inv; v[s].y *= inv; v[s].z *= inv; v[s].w *= inv;
        ((float4*)r)[t + s * 256] = v[s];
    }
}

// ------------------------- CAM softmax -------------------------------------
// attn[c,d] = softmax_d(rowmax_c(E) - E[c,d]); write transposed AT[d][c]
__global__ void cam_softmax(const float* __restrict__ E, float* __restrict__ AT)
{
    int c = blockIdx.x, b = blockIdx.y;
    const float* row = E + ((long long)b * 512 + c) * 512;
    float* outb = AT + (long long)b * 512 * 512;
    int t = threadIdx.x;

    float e0 = row[t], e1 = row[t + 256];
    __shared__ float red[256];

    red[t] = fmaxf(e0, e1); __syncthreads();
    for (int o = 128; o > 0; o >>= 1) {
        if (t < o) red[t] = fmaxf(red[t], red[t + o]);
        __syncthreads();
    }
    float rowmax = red[0]; __syncthreads();

    float t0 = rowmax - e0, t1 = rowmax - e1;
    red[t] = fmaxf(t0, t1); __syncthreads();
    for (int o = 128; o > 0; o >>= 1) {
        if (t < o) red[t] = fmaxf(red[t], red[t + o]);
        __syncthreads();
    }
    float m2 = red[0]; __syncthreads();

    float x0 = __expf(t0 - m2), x1 = __expf(t1 - m2);
    red[t] = x0 + x1; __syncthreads();
    for (int o = 128; o > 0; o >>= 1) {
        if (t < o) red[t] += red[t + o];
        __syncthreads();
    }
    float inv = 1.f / red[0];
    outb[(long long)t * 512 + c] = x0 * inv;
    outb[(long long)(t + 256) * 512 + c] = x1 * inv;
}

// ------------------------- transpose [512,4096] -> [4096,512] per batch ----
__global__ void transpose_cn(const float* __restrict__ in, float* __restrict__ out)
{
    __shared__ float tile[32][33];
    int b = blockIdx.z;
    int n0 = blockIdx.x * 32, c0 = blockIdx.y * 32;
    const float* ib = in + (long long)b * 512 * 4096;
    float* ob = out + (long long)b * 4096 * 512;
    int tx = threadIdx.x, ty = threadIdx.y;
#pragma unroll
    for (int s = 0; s < 32; s += 8)
        tile[ty + s][tx] = ib[(long long)(c0 + ty + s) * 4096 + n0 + tx];
    __syncthreads();
#pragma unroll
    for (int s = 0; s < 32; s += 8)
        ob[(long long)(n0 + ty + s) * 512 + c0 + tx] = tile[tx][ty + s];
}

// ---------------------------------------------------------------------------
extern "C" void kernel_launch(void* const* d_in, const int* in_sizes, int n_in,
                              void* d_out, int out_size)
{
    (void)in_sizes; (void)n_in; (void)out_size;
    const float* x      = (const float*)d_in[0];
    const float* w5a    = (const float*)d_in[1];
    const float* bn5a_s = (const float*)d_in[2];
    const float* bn5a_b = (const float*)d_in[3];
    const float* bn5a_m = (const float*)d_in[4];
    const float* bn5a_v = (const float*)d_in[5];
    const float* w5c    = (const float*)d_in[6];
    const float* bn5c_s = (const float*)d_in[7];
    const float* bn5c_b = (const float*)d_in[8];
    const float* bn5c_m = (const float*)d_in[9];
    const float* bn5c_v = (const float*)d_in[10];
    const float* wq     = (const float*)d_in[11];
    const float* qb     = (const float*)d_in[12];
    const float* wk     = (const float*)d_in[13];
    const float* kb     = (const float*)d_in[14];
    const float* wv     = (const float*)d_in[15];
    const float* vb     = (const float*)d_in[16];
    const float* pgamma = (const float*)d_in[17];
    const float* cgamma = (const float*)d_in[18];
    const float* w51    = (const float*)d_in[19];
    const float* bn51_s = (const float*)d_in[20];
    const float* bn51_b = (const float*)d_in[21];
    const float* bn51_m = (const float*)d_in[22];
    const float* bn51_v = (const float*)d_in[23];
    const float* w52    = (const float*)d_in[24];
    const float* bn52_s = (const float*)d_in[25];
    const float* bn52_b = (const float*)d_in[26];
    const float* bn52_m = (const float*)d_in[27];
    const float* bn52_v = (const float*)d_in[28];
    const float* w8     = (const float*)d_in[29];
    const float* b8     = (const float*)d_in[30];
    float* out = (float*)d_out;

    float *wt5a, *wt5c, *wt51, *wt52, *wqT, *wkT, *wvT, *w8T;
    float *feat1, *feat2, *q, *k, *vT, *G, *sa, *sc, *saconv, *fsum, *fT, *camE, *camA;
    cudaGetSymbolAddress((void**)&wt5a, g_wt5a);
    cudaGetSymbolAddress((void**)&wt5c, g_wt5c);
    cudaGetSymbolAddress((void**)&wt51, g_wt51);
    cudaGetSymbolAddress((void**)&wt52, g_wt52);
    cudaGetSymbolAddress((void**)&wqT, g_wqT);
    cudaGetSymbolAddress((void**)&wkT, g_wkT);
    cudaGetSymbolAddress((void**)&wvT, g_wvT);
    cudaGetSymbolAddress((void**)&w8T, g_w8T);
    cudaGetSymbolAddress((void**)&feat1, g_feat1);
    cudaGetSymbolAddress((void**)&feat2, g_feat2);
    cudaGetSymbolAddress((void**)&q, g_q);
    cudaGetSymbolAddress((void**)&k, g_k);
    cudaGetSymbolAddress((void**)&vT, g_vT);
    cudaGetSymbolAddress((void**)&G, g_G);
    cudaGetSymbolAddress((void**)&sa, g_sa);
    cudaGetSymbolAddress((void**)&sc, g_sc);
    cudaGetSymbolAddress((void**)&saconv, g_saconv);
    cudaGetSymbolAddress((void**)&fsum, g_fsum);
    cudaGetSymbolAddress((void**)&fT, g_fT);
    cudaGetSymbolAddress((void**)&camE, g_camE);
    cudaGetSymbolAddress((void**)&camA, g_camA);

    // ---- weight re-layout ----
    wtrans3x3<<<4096, 256>>>(w5a, wt5a, 2048);
    wtrans3x3<<<4096, 256>>>(w5c, wt5c, 2048);
    wtrans3x3<<<4096, 256>>>(w51, wt51, 512);
    wtrans3x3<<<4096, 256>>>(w52, wt52, 512);
    wtrans1x1<<<(512 * 64 + 255) / 256, 256>>>(wq, wqT, 512, 64);
    wtrans1x1<<<(512 * 64 + 255) / 256, 256>>>(wk, wkT, 512, 64);
    wtrans1x1<<<(512 * 512 + 255) / 256, 256>>>(wv, wvT, 512, 512);
    wtrans1x1<<<(512 * 19 + 255) / 256, 256>>>(w8, w8T, 512, 19);

    const dim3 cgrid(32, 4, BATCH);

    // ---- stem convs ----
    conv3x3_kernel<<<cgrid, 256>>>(x, wt5a, 2048, bn5a_s, bn5a_b, bn5a_m, bn5a_v,
                                   nullptr, feat1);
    conv3x3_kernel<<<cgrid, 256>>>(x, wt5c, 2048, bn5c_s, bn5c_b, bn5c_m, bn5c_v,
                                   nullptr, feat2);

    const long long sF = 512LL * 4096;   // per-batch feature stride
    const long long sQ = 64LL * 4096;
    const long long sVT = 4096LL * 512;
    const long long sG = 4096LL * 4096;

    // ---- PAM ----
    gemm_tn_kernel<<<dim3(32, 1, BATCH), 256>>>(wqT, 0, 64, feat1, sF, 4096,
                                                q, sQ, 4096, 64, 512,
                                                1, qb, nullptr, 0, nullptr);
    gemm_tn_kernel<<<dim3(32, 1, BATCH), 256>>>(wkT, 0, 64, feat1, sF, 4096,
                                                k, sQ, 4096, 64, 512,
                                                1, kb, nullptr, 0, nullptr);
    // v, stored transposed: vT[n][c]
    gemm_tn_kernel<<<dim3(32, 4, BATCH), 256>>>(wvT, 0, 512, feat1, sF, 4096,
                                                vT, sVT, 512, 512, 512,
                                                3, vb, nullptr, 0, nullptr);
    // G[n][m] = energy^T = sum_d k[d,n] q[d,m]
    gemm_tn_kernel<<<dim3(32, 32, BATCH), 256>>>(k, sQ, 4096, q, sQ, 4096,
                                                 G, sG, 4096, 4096, 64,
                                                 0, nullptr, nullptr, 0, nullptr);
    // softmax over energy axis=1  == row softmax of G
    softmax_rows4096<<<BATCH * 4096, 256>>>(G);
    // sa_feat[c][m] = gamma * sum_n vT[n][c] * G[n][m] + feat1
    gemm_tn_kernel<<<dim3(32, 4, BATCH), 256>>>(vT, sVT, 512, G, sG, 4096,
                                                sa, sF, 4096, 512, 4096,
                                                2, nullptr, feat1, sF, pgamma);
    conv3x3_kernel<<<cgrid, 256>>>(sa, wt51, 512, bn51_s, bn51_b, bn51_m, bn51_v,
                                   nullptr, saconv);

    // ---- CAM ----
    transpose_cn<<<dim3(128, 16, BATCH), dim3(32, 8)>>>(feat2, fT);
    // E[c][d] = sum_n f[c,n] f[d,n]
    gemm_tn_kernel<<<dim3(4, 4, BATCH), 256>>>(fT, sVT, 512, fT, sVT, 512,
                                               camE, 512LL * 512, 512, 512, 4096,
                                               0, nullptr, nullptr, 0, nullptr);
    cam_softmax<<<dim3(512, BATCH), 256>>>(camE, camA);
    // sc_feat[c][n] = gamma * sum_d attnT[d][c] * feat2[d][n] + feat2
    gemm_tn_kernel<<<dim3(32, 4, BATCH), 256>>>(camA, 512LL * 512, 512, feat2, sF, 4096,
                                                sc, sF, 4096, 512, 512,
                                                2, nullptr, feat2, sF, cgamma);
    conv3x3_kernel<<<cgrid, 256>>>(sc, wt52, 512, bn52_s, bn52_b, bn52_m, bn52_v,
                                   saconv, fsum);   // + sa_conv residual = feat_sum

    // ---- final 1x1 conv ----
    gemm_tn_kernel<<<dim3(32, 1, BATCH), 256>>>(w8T, 0, 19, fsum, sF, 4096,
                                                out, 19LL * 4096, 4096, 19, 512,
                                                1, b8, nullptr, 0, nullptr);
}

// round 6
// speedup vs baseline: 1.7027x; 1.7027x over previous
#include <cuda_runtime.h>
#include <cuda_bf16.h>
#include <math.h>

// ---------------------------------------------------------------------------
// DANet head — bf16 split (hi/lo, 3-term) tensor-core version, m16n8k16 MMA.
// R6: conv weights pre-split into packed bf16 hi/lo planes at relayout time.
// Shapes: B=4, Cin=2048, H=W=64 (N=4096 px/batch), Ci=512, Cq=64, Cout=19.
// ---------------------------------------------------------------------------

#define BATCH 4
#define NPIX  4096
#define COUT  512

// ------------------------- scratch (device globals) ------------------------
// conv weights: packed u32 planes, [tap][ci_pair][co]; hi and lo separately.
__device__ unsigned g_wt5a_hi[9u * 1024u * 512u];
__device__ unsigned g_wt5a_lo[9u * 1024u * 512u];
__device__ unsigned g_wt5c_hi[9u * 1024u * 512u];
__device__ unsigned g_wt5c_lo[9u * 1024u * 512u];
__device__ unsigned g_wt51_hi[9u * 256u * 512u];
__device__ unsigned g_wt51_lo[9u * 256u * 512u];
__device__ unsigned g_wt52_hi[9u * 256u * 512u];
__device__ unsigned g_wt52_lo[9u * 256u * 512u];
__device__ float g_wqT[512 * 64];                  // [ci][co]
__device__ float g_wkT[512 * 64];
__device__ float g_wvT[512 * 512];
__device__ float g_w8T[512 * 19];
__device__ float g_feat1[(size_t)BATCH * 512 * 4096];
__device__ float g_feat2[(size_t)BATCH * 512 * 4096];
__device__ float g_q[(size_t)BATCH * 64 * 4096];
__device__ float g_k[(size_t)BATCH * 64 * 4096];
__device__ float g_vT[(size_t)BATCH * 4096 * 512]; // [n][c]
__device__ float g_G[(size_t)BATCH * 4096 * 4096]; // energy^T, row-softmaxed
__device__ float g_sa[(size_t)BATCH * 512 * 4096];
__device__ float g_sc[(size_t)BATCH * 512 * 4096];
__device__ float g_saconv[(size_t)BATCH * 512 * 4096];
__device__ float g_fsum[(size_t)BATCH * 512 * 4096];
__device__ float g_fT[(size_t)BATCH * 4096 * 512]; // feat2 transposed per batch
__device__ float g_camE[(size_t)BATCH * 512 * 512];
__device__ float g_camA[(size_t)BATCH * 512 * 512]; // attn^T  [d][c]

// ------------------------- bf16 split helpers -------------------------------
__device__ __forceinline__ void split2(float x0, float x1,
                                       unsigned& hi, unsigned& lo)
{
    __nv_bfloat16 h0 = __float2bfloat16_rn(x0);
    __nv_bfloat16 h1 = __float2bfloat16_rn(x1);
    __nv_bfloat16 l0 = __float2bfloat16_rn(x0 - __bfloat162float(h0));
    __nv_bfloat16 l1 = __float2bfloat16_rn(x1 - __bfloat162float(h1));
    unsigned h0b = (unsigned)__bfloat16_as_ushort(h0);
    unsigned h1b = (unsigned)__bfloat16_as_ushort(h1);
    unsigned l0b = (unsigned)__bfloat16_as_ushort(l0);
    unsigned l1b = (unsigned)__bfloat16_as_ushort(l1);
    hi = h0b | (h1b << 16);
    lo = l0b | (l1b << 16);
}

__device__ __forceinline__ void mma_bf16(float* d, const unsigned* a, const unsigned* b) {
    asm volatile(
        "mma.sync.aligned.m16n8k16.row.col.f32.bf16.bf16.f32 "
        "{%0,%1,%2,%3}, {%4,%5,%6,%7}, {%8,%9}, {%0,%1,%2,%3};\n"
        : "+f"(d[0]), "+f"(d[1]), "+f"(d[2]), "+f"(d[3])
        : "r"(a[0]), "r"(a[1]), "r"(a[2]), "r"(a[3]), "r"(b[0]), "r"(b[1]));
}

// ------------------------- weight re-layout ---------------------------------
// W[co][ci][3x3] -> packed hi/lo planes [tap][ci_pair][co]  (Cout = 512)
__global__ void wtrans3x3(const float* __restrict__ W,
                          unsigned* __restrict__ Whi, unsigned* __restrict__ Wlo,
                          int Cin)
{
    int cp2 = Cin >> 1;
    long long n = (long long)512 * cp2 * 9;
    long long cs = (long long)cp2 * 512;
    for (long long i = (long long)blockIdx.x * blockDim.x + threadIdx.x; i < n;
         i += (long long)gridDim.x * blockDim.x) {
        int tap = (int)(i / cs);
        long long r = i - (long long)tap * cs;
        int cp = (int)(r / 512);
        int co = (int)(r - (long long)cp * 512);
        float w0 = W[((long long)co * Cin + 2 * cp) * 9 + tap];
        float w1 = W[((long long)co * Cin + 2 * cp + 1) * 9 + tap];
        unsigned hi, lo;
        split2(w0, w1, hi, lo);
        Whi[i] = hi;
        Wlo[i] = lo;
    }
}

// W[co][ci] -> Wt[ci][co]
__global__ void wtrans1x1(const float* __restrict__ W, float* __restrict__ Wt,
                          int Cin, int Cout)
{
    int i = blockIdx.x * blockDim.x + threadIdx.x;
    if (i < Cin * Cout) {
        int ci = i / Cout, co = i - ci * Cout;
        Wt[i] = W[co * Cin + ci];
    }
}

// Padded row width for MMA-operand smem tiles (u32 words per k-row)
#define LDW 136

// ------------------------- 3x3 conv (bf16x3 MMA) + BN + ReLU (+res) --------
__global__ void __launch_bounds__(256, 1)
conv3x3_bf16(const float* __restrict__ X,
             const unsigned* __restrict__ Whi, const unsigned* __restrict__ Wlo,
             int Cin,
             const float* __restrict__ bns, const float* __restrict__ bnb,
             const float* __restrict__ bnm, const float* __restrict__ bnv,
             const float* __restrict__ res, float* __restrict__ Y)
{
    __shared__ unsigned AsHi[16][LDW], AsLo[16][LDW];
    __shared__ unsigned BsHi[16][LDW], BsLo[16][LDW];

    const int p0  = blockIdx.x * 128;
    const int co0 = blockIdx.y * 128;
    const int b   = blockIdx.z;
    const float* Xb = X + (size_t)b * Cin * NPIX;
    const int cp2 = Cin >> 1;   // ci pairs

    const int tid  = threadIdx.x;
    const int lane = tid & 31;
    const int warp = tid >> 5;
    const int wm = warp >> 2;          // 0..1
    const int wn = warp & 3;           // 0..3
    const int e    = tid & 127;        // load column (fixed per thread)
    const int kprow = tid >> 7;        // 0..1

    float acc[4][4][4];
#pragma unroll
    for (int mi = 0; mi < 4; mi++)
#pragma unroll
        for (int ni = 0; ni < 4; ni++)
#pragma unroll
            for (int r = 0; r < 4; r++) acc[mi][ni][r] = 0.f;

    const int p  = p0 + e;
    const int py = p >> 6, px = p & 63;
    const int q    = lane & 3;
    const int r    = lane >> 2;
    const int mrow = wm * 64 + r;
    const int ncol = wn * 32 + r;

    for (int tap = 0; tap < 9; tap++) {
        const int dy = tap / 3 - 1, dx = tap % 3 - 1;
        const size_t wbase = (size_t)tap * cp2 * COUT + (co0 + e);
        const unsigned* WtapHi = Whi + wbase;
        const unsigned* WtapLo = Wlo + wbase;

        const int yy = py + dy, xx = px + dx;
        const bool ok = ((unsigned)yy < 64u) && ((unsigned)xx < 64u);
        const int pofs = ok ? ((yy << 6) + xx) : 0;

        for (int c0 = 0; c0 < Cin; c0 += 32) {
            const unsigned* WcHi = WtapHi + (size_t)(c0 >> 1) * COUT;
            const unsigned* WcLo = WtapLo + (size_t)(c0 >> 1) * COUT;
            const float* Xc = Xb + (size_t)c0 * NPIX + pofs;
#pragma unroll
            for (int s = 0; s < 8; s++) {
                int kp = kprow + 2 * s;            // 0..15 (= ci pair in chunk)
                AsHi[kp][e] = WcHi[(size_t)kp * COUT];
                AsLo[kp][e] = WcLo[(size_t)kp * COUT];
                float b0 = ok ? Xc[(size_t)(2 * kp) * NPIX] : 0.f;
                float b1 = ok ? Xc[(size_t)(2 * kp + 1) * NPIX] : 0.f;
                unsigned hi, lo;
                split2(b0, b1, hi, lo);
                BsHi[kp][e] = hi; BsLo[kp][e] = lo;
            }
            __syncthreads();
#pragma unroll
            for (int sl = 0; sl < 2; sl++) {
                const int kb = sl * 8;
                unsigned ahi[4][4], alo[4][4];
#pragma unroll
                for (int mi = 0; mi < 4; mi++) {
                    int m = mrow + mi * 16;
                    ahi[mi][0] = AsHi[kb + q][m];
                    ahi[mi][1] = AsHi[kb + q][m + 8];
                    ahi[mi][2] = AsHi[kb + q + 4][m];
                    ahi[mi][3] = AsHi[kb + q + 4][m + 8];
                    alo[mi][0] = AsLo[kb + q][m];
                    alo[mi][1] = AsLo[kb + q][m + 8];
                    alo[mi][2] = AsLo[kb + q + 4][m];
                    alo[mi][3] = AsLo[kb + q + 4][m + 8];
                }
#pragma unroll
                for (int ni = 0; ni < 4; ni++) {
                    int n = ncol + ni * 8;
                    unsigned bhi[2], blo[2];
                    bhi[0] = BsHi[kb + q][n];
                    bhi[1] = BsHi[kb + q + 4][n];
                    blo[0] = BsLo[kb + q][n];
                    blo[1] = BsLo[kb + q + 4][n];
#pragma unroll
                    for (int mi = 0; mi < 4; mi++) {
                        mma_bf16(acc[mi][ni], ahi[mi], bhi);
                        mma_bf16(acc[mi][ni], ahi[mi], blo);
                        mma_bf16(acc[mi][ni], alo[mi], bhi);
                    }
                }
            }
            __syncthreads();
        }
    }

    // epilogue: BN + ReLU (+ residual)
#pragma unroll
    for (int mi = 0; mi < 4; mi++) {
        int r0 = co0 + wm * 64 + mi * 16 + r;
        int r1 = r0 + 8;
        float sc0 = bns[r0] * rsqrtf(bnv[r0] + 1e-5f);
        float sh0 = bnb[r0] - sc0 * bnm[r0];
        float sc1 = bns[r1] * rsqrtf(bnv[r1] + 1e-5f);
        float sh1 = bnb[r1] - sc1 * bnm[r1];
#pragma unroll
        for (int ni = 0; ni < 4; ni++) {
            int c = p0 + wn * 32 + ni * 8 + 2 * q;
            size_t o0 = ((size_t)b * COUT + r0) * NPIX + c;
            size_t o1 = ((size_t)b * COUT + r1) * NPIX + c;
            float v00 = fmaxf(fmaf(sc0, acc[mi][ni][0], sh0), 0.f);
            float v01 = fmaxf(fmaf(sc0, acc[mi][ni][1], sh0), 0.f);
            float v10 = fmaxf(fmaf(sc1, acc[mi][ni][2], sh1), 0.f);
            float v11 = fmaxf(fmaf(sc1, acc[mi][ni][3], sh1), 0.f);
            if (res) {
                v00 += res[o0]; v01 += res[o0 + 1];
                v10 += res[o1]; v11 += res[o1 + 1];
            }
            *(float2*)&Y[o0] = make_float2(v00, v01);
            *(float2*)&Y[o1] = make_float2(v10, v11);
        }
    }
}

// ------------------------- generic TN GEMM (bf16x3 MMA) ----------------------
// C[i,j] = sum_k A[k*lda+i] * B[k*ldb+j]  (per blockIdx.z batch, strides s*)
// epi: 0 store | 1 +bias[i] | 2 gamma*acc + res[i*ldc+j] | 4 +bias[j]
__global__ void __launch_bounds__(256, 1)
gemm_bf16(const float* __restrict__ A, long long sA, int lda,
          const float* __restrict__ B, long long sB, int ldb,
          float* __restrict__ C, long long sC, int ldc,
          int M, int K, int epi,
          const float* __restrict__ bias,
          const float* __restrict__ res, long long sRes,
          const float* __restrict__ gammaPtr)
{
    __shared__ unsigned AsHi[16][LDW], AsLo[16][LDW];
    __shared__ unsigned BsHi[16][LDW], BsLo[16][LDW];

    const int bj = blockIdx.x * 128;
    const int bi = blockIdx.y * 128;
    const int z = blockIdx.z;
    A += (long long)z * sA;
    B += (long long)z * sB;
    C += (long long)z * sC;

    const int tid  = threadIdx.x;
    const int lane = tid & 31;
    const int warp = tid >> 5;
    const int wm = warp >> 2, wn = warp & 3;
    const int e    = tid & 127;
    const int kprow = tid >> 7;

    float acc[4][4][4];
#pragma unroll
    for (int mi = 0; mi < 4; mi++)
#pragma unroll
        for (int ni = 0; ni < 4; ni++)
#pragma unroll
            for (int rr = 0; rr < 4; rr++) acc[mi][ni][rr] = 0.f;

    const bool aok = (bi + e) < M;
    const int q    = lane & 3;
    const int r    = lane >> 2;
    const int mrow = wm * 64 + r;
    const int ncol = wn * 32 + r;

    for (int k0 = 0; k0 < K; k0 += 32) {
#pragma unroll
        for (int s = 0; s < 8; s++) {
            int kp = kprow + 2 * s;
            float a0 = aok ? A[(long long)(k0 + 2 * kp) * lda + bi + e] : 0.f;
            float a1 = aok ? A[(long long)(k0 + 2 * kp + 1) * lda + bi + e] : 0.f;
            unsigned hi, lo;
            split2(a0, a1, hi, lo);
            AsHi[kp][e] = hi; AsLo[kp][e] = lo;
            float b0 = B[(long long)(k0 + 2 * kp) * ldb + bj + e];
            float b1 = B[(long long)(k0 + 2 * kp + 1) * ldb + bj + e];
            split2(b0, b1, hi, lo);
            BsHi[kp][e] = hi; BsLo[kp][e] = lo;
        }
        __syncthreads();
#pragma unroll
        for (int sl = 0; sl < 2; sl++) {
            const int kb = sl * 8;
            unsigned ahi[4][4], alo[4][4];
#pragma unroll
            for (int mi = 0; mi < 4; mi++) {
                int m = mrow + mi * 16;
                ahi[mi][0] = AsHi[kb + q][m];
                ahi[mi][1] = AsHi[kb + q][m + 8];
                ahi[mi][2] = AsHi[kb + q + 4][m];
                ahi[mi][3] = AsHi[kb + q + 4][m + 8];
                alo[mi][0] = AsLo[kb + q][m];
                alo[mi][1] = AsLo[kb + q][m + 8];
                alo[mi][2] = AsLo[kb + q + 4][m];
                alo[mi][3] = AsLo[kb + q + 4][m + 8];
            }
#pragma unroll
            for (int ni = 0; ni < 4; ni++) {
                int n = ncol + ni * 8;
                unsigned bhi[2], blo[2];
                bhi[0] = BsHi[kb + q][n];
                bhi[1] = BsHi[kb + q + 4][n];
                blo[0] = BsLo[kb + q][n];
                blo[1] = BsLo[kb + q + 4][n];
#pragma unroll
                for (int mi = 0; mi < 4; mi++) {
                    mma_bf16(acc[mi][ni], ahi[mi], bhi);
                    mma_bf16(acc[mi][ni], ahi[mi], blo);
                    mma_bf16(acc[mi][ni], alo[mi], bhi);
                }
            }
        }
        __syncthreads();
    }

    const float gamma = (epi == 2) ? *gammaPtr : 1.f;
    const float* rz = (epi == 2) ? (res + (long long)z * sRes) : nullptr;

#pragma unroll
    for (int mi = 0; mi < 4; mi++) {
        int r0 = bi + wm * 64 + mi * 16 + r;
        int r1 = r0 + 8;
#pragma unroll
        for (int ni = 0; ni < 4; ni++) {
            int c = bj + wn * 32 + ni * 8 + 2 * q;
#pragma unroll
            for (int h = 0; h < 2; h++) {
                int rr = h ? r1 : r0;
                if (rr >= M) continue;
                float v0 = acc[mi][ni][h * 2 + 0];
                float v1 = acc[mi][ni][h * 2 + 1];
                long long o = (long long)rr * ldc + c;
                if (epi == 1) {
                    v0 += bias[rr]; v1 += bias[rr];
                } else if (epi == 2) {
                    v0 = fmaf(gamma, v0, rz[o]);
                    v1 = fmaf(gamma, v1, rz[o + 1]);
                } else if (epi == 4) {
                    v0 += bias[c]; v1 += bias[c + 1];
                }
                *(float2*)&C[o] = make_float2(v0, v1);
            }
        }
    }
}

// ------------------------- PAM row softmax (rows of 4096, in-place) --------
__global__ void softmax_rows4096(float* __restrict__ G)
{
    long long row = blockIdx.x;
    float* r = G + row * 4096;
    int t = threadIdx.x;

    float4 v[4];
    float mx = -INFINITY;
#pragma unroll
    for (int s = 0; s < 4; s++) {
        v[s] = ((const float4*)r)[t + s * 256];
        mx = fmaxf(mx, fmaxf(fmaxf(v[s].x, v[s].y), fmaxf(v[s].z, v[s].w)));
    }
    __shared__ float red[256];
    red[t] = mx; __syncthreads();
    for (int o = 128; o > 0; o >>= 1) {
        if (t < o) red[t] = fmaxf(red[t], red[t + o]);
        __syncthreads();
    }
    mx = red[0]; __syncthreads();

    float sum = 0.f;
#pragma unroll
    for (int s = 0; s < 4; s++) {
        v[s].x = __expf(v[s].x - mx);
        v[s].y = __expf(v[s].y - mx);
        v[s].z = __expf(v[s].z - mx);
        v[s].w = __expf(v[s].w - mx);
        sum += v[s].x + v[s].y + v[s].z + v[s].w;
    }
    red[t] = sum; __syncthreads();
    for (int o = 128; o > 0; o >>= 1) {
        if (t < o) red[t] += red[t + o];
        __syncthreads();
    }
    float inv = 1.f / red[0];
#pragma unroll
    for (int s = 0; s < 4; s++) {
        v[s].x *= inv; v[s].y *= inv; v[s].z *= inv; v[s].w *= inv;
        ((float4*)r)[t + s * 256] = v[s];
    }
}

// ------------------------- CAM softmax -------------------------------------
// attn[c,d] = softmax_d(rowmax_c(E) - E[c,d]); write transposed AT[d][c]
__global__ void cam_softmax(const float* __restrict__ E, float* __restrict__ AT)
{
    int c = blockIdx.x, b = blockIdx.y;
    const float* row = E + ((long long)b * 512 + c) * 512;
    float* outb = AT + (long long)b * 512 * 512;
    int t = threadIdx.x;

    float e0 = row[t], e1 = row[t + 256];
    __shared__ float red[256];

    red[t] = fmaxf(e0, e1); __syncthreads();
    for (int o = 128; o > 0; o >>= 1) {
        if (t < o) red[t] = fmaxf(red[t], red[t + o]);
        __syncthreads();
    }
    float rowmax = red[0]; __syncthreads();

    float t0 = rowmax - e0, t1 = rowmax - e1;
    red[t] = fmaxf(t0, t1); __syncthreads();
    for (int o = 128; o > 0; o >>= 1) {
        if (t < o) red[t] = fmaxf(red[t], red[t + o]);
        __syncthreads();
    }
    float m2 = red[0]; __syncthreads();

    float x0 = __expf(t0 - m2), x1 = __expf(t1 - m2);
    red[t] = x0 + x1; __syncthreads();
    for (int o = 128; o > 0; o >>= 1) {
        if (t < o) red[t] += red[t + o];
        __syncthreads();
    }
    float inv = 1.f / red[0];
    outb[(long long)t * 512 + c] = x0 * inv;
    outb[(long long)(t + 256) * 512 + c] = x1 * inv;
}

// ------------------------- transpose [512,4096] -> [4096,512] per batch ----
__global__ void transpose_cn(const float* __restrict__ in, float* __restrict__ out)
{
    __shared__ float tile[32][33];
    int b = blockIdx.z;
    int n0 = blockIdx.x * 32, c0 = blockIdx.y * 32;
    const float* ib = in + (long long)b * 512 * 4096;
    float* ob = out + (long long)b * 4096 * 512;
    int tx = threadIdx.x, ty = threadIdx.y;
#pragma unroll
    for (int s = 0; s < 32; s += 8)
        tile[ty + s][tx] = ib[(long long)(c0 + ty + s) * 4096 + n0 + tx];
    __syncthreads();
#pragma unroll
    for (int s = 0; s < 32; s += 8)
        ob[(long long)(n0 + ty + s) * 512 + c0 + tx] = tile[tx][ty + s];
}

// ---------------------------------------------------------------------------
extern "C" void kernel_launch(void* const* d_in, const int* in_sizes, int n_in,
                              void* d_out, int out_size)
{
    (void)in_sizes; (void)n_in; (void)out_size;
    const float* x      = (const float*)d_in[0];
    const float* w5a    = (const float*)d_in[1];
    const float* bn5a_s = (const float*)d_in[2];
    const float* bn5a_b = (const float*)d_in[3];
    const float* bn5a_m = (const float*)d_in[4];
    const float* bn5a_v = (const float*)d_in[5];
    const float* w5c    = (const float*)d_in[6];
    const float* bn5c_s = (const float*)d_in[7];
    const float* bn5c_b = (const float*)d_in[8];
    const float* bn5c_m = (const float*)d_in[9];
    const float* bn5c_v = (const float*)d_in[10];
    const float* wq     = (const float*)d_in[11];
    const float* qb     = (const float*)d_in[12];
    const float* wk     = (const float*)d_in[13];
    const float* kb     = (const float*)d_in[14];
    const float* wv     = (const float*)d_in[15];
    const float* vb     = (const float*)d_in[16];
    const float* pgamma = (const float*)d_in[17];
    const float* cgamma = (const float*)d_in[18];
    const float* w51    = (const float*)d_in[19];
    const float* bn51_s = (const float*)d_in[20];
    const float* bn51_b = (const float*)d_in[21];
    const float* bn51_m = (const float*)d_in[22];
    const float* bn51_v = (const float*)d_in[23];
    const float* w52    = (const float*)d_in[24];
    const float* bn52_s = (const float*)d_in[25];
    const float* bn52_b = (const float*)d_in[26];
    const float* bn52_m = (const float*)d_in[27];
    const float* bn52_v = (const float*)d_in[28];
    const float* w8     = (const float*)d_in[29];
    const float* b8     = (const float*)d_in[30];
    float* out = (float*)d_out;

    unsigned *wt5aH, *wt5aL, *wt5cH, *wt5cL, *wt51H, *wt51L, *wt52H, *wt52L;
    float *wqT, *wkT, *wvT, *w8T;
    float *feat1, *feat2, *q, *k, *vT, *G, *sa, *sc, *saconv, *fsum, *fT, *camE, *camA;
    cudaGetSymbolAddress((void**)&wt5aH, g_wt5a_hi);
    cudaGetSymbolAddress((void**)&wt5aL, g_wt5a_lo);
    cudaGetSymbolAddress((void**)&wt5cH, g_wt5c_hi);
    cudaGetSymbolAddress((void**)&wt5cL, g_wt5c_lo);
    cudaGetSymbolAddress((void**)&wt51H, g_wt51_hi);
    cudaGetSymbolAddress((void**)&wt51L, g_wt51_lo);
    cudaGetSymbolAddress((void**)&wt52H, g_wt52_hi);
    cudaGetSymbolAddress((void**)&wt52L, g_wt52_lo);
    cudaGetSymbolAddress((void**)&wqT, g_wqT);
    cudaGetSymbolAddress((void**)&wkT, g_wkT);
    cudaGetSymbolAddress((void**)&wvT, g_wvT);
    cudaGetSymbolAddress((void**)&w8T, g_w8T);
    cudaGetSymbolAddress((void**)&feat1, g_feat1);
    cudaGetSymbolAddress((void**)&feat2, g_feat2);
    cudaGetSymbolAddress((void**)&q, g_q);
    cudaGetSymbolAddress((void**)&k, g_k);
    cudaGetSymbolAddress((void**)&vT, g_vT);
    cudaGetSymbolAddress((void**)&G, g_G);
    cudaGetSymbolAddress((void**)&sa, g_sa);
    cudaGetSymbolAddress((void**)&sc, g_sc);
    cudaGetSymbolAddress((void**)&saconv, g_saconv);
    cudaGetSymbolAddress((void**)&fsum, g_fsum);
    cudaGetSymbolAddress((void**)&fT, g_fT);
    cudaGetSymbolAddress((void**)&camE, g_camE);
    cudaGetSymbolAddress((void**)&camA, g_camA);

    // ---- weight re-layout (+ bf16 hi/lo pre-split for convs) ----
    wtrans3x3<<<4096, 256>>>(w5a, wt5aH, wt5aL, 2048);
    wtrans3x3<<<4096, 256>>>(w5c, wt5cH, wt5cL, 2048);
    wtrans3x3<<<4096, 256>>>(w51, wt51H, wt51L, 512);
    wtrans3x3<<<4096, 256>>>(w52, wt52H, wt52L, 512);
    wtrans1x1<<<(512 * 64 + 255) / 256, 256>>>(wq, wqT, 512, 64);
    wtrans1x1<<<(512 * 64 + 255) / 256, 256>>>(wk, wkT, 512, 64);
    wtrans1x1<<<(512 * 512 + 255) / 256, 256>>>(wv, wvT, 512, 512);
    wtrans1x1<<<(512 * 19 + 255) / 256, 256>>>(w8, w8T, 512, 19);

    const dim3 cgrid(32, 4, BATCH);

    // ---- stem convs ----
    conv3x3_bf16<<<cgrid, 256>>>(x, wt5aH, wt5aL, 2048,
                                 bn5a_s, bn5a_b, bn5a_m, bn5a_v, nullptr, feat1);
    conv3x3_bf16<<<cgrid, 256>>>(x, wt5cH, wt5cL, 2048,
                                 bn5c_s, bn5c_b, bn5c_m, bn5c_v, nullptr, feat2);

    const long long sF = 512LL * 4096;   // per-batch feature stride
    const long long sQ = 64LL * 4096;
    const long long sVT = 4096LL * 512;
    const long long sG = 4096LL * 4096;

    // ---- PAM ----
    gemm_bf16<<<dim3(32, 1, BATCH), 256>>>(wqT, 0, 64, feat1, sF, 4096,
                                           q, sQ, 4096, 64, 512,
                                           1, qb, nullptr, 0, nullptr);
    gemm_bf16<<<dim3(32, 1, BATCH), 256>>>(wkT, 0, 64, feat1, sF, 4096,
                                           k, sQ, 4096, 64, 512,
                                           1, kb, nullptr, 0, nullptr);
    // vT[n][c] = sum_ci feat1[ci][n] * wvT[ci][c]  (+ bias per column c)
    gemm_bf16<<<dim3(4, 32, BATCH), 256>>>(feat1, sF, 4096, wvT, 0, 512,
                                           vT, sVT, 512, 4096, 512,
                                           4, vb, nullptr, 0, nullptr);
    // G[n][m] = energy^T = sum_d k[d,n] q[d,m]
    gemm_bf16<<<dim3(32, 32, BATCH), 256>>>(k, sQ, 4096, q, sQ, 4096,
                                            G, sG, 4096, 4096, 64,
                                            0, nullptr, nullptr, 0, nullptr);
    // softmax over energy axis=1  == row softmax of G
    softmax_rows4096<<<BATCH * 4096, 256>>>(G);
    // sa_feat[c][m] = gamma * sum_n vT[n][c] * G[n][m] + feat1
    gemm_bf16<<<dim3(32, 4, BATCH), 256>>>(vT, sVT, 512, G, sG, 4096,
                                           sa, sF, 4096, 512, 4096,
                                           2, nullptr, feat1, sF, pgamma);
    conv3x3_bf16<<<cgrid, 256>>>(sa, wt51H, wt51L, 512,
                                 bn51_s, bn51_b, bn51_m, bn51_v, nullptr, saconv);

    // ---- CAM ----
    transpose_cn<<<dim3(128, 16, BATCH), dim3(32, 8)>>>(feat2, fT);
    // E[c][d] = sum_n f[c,n] f[d,n]
    gemm_bf16<<<dim3(4, 4, BATCH), 256>>>(fT, sVT, 512, fT, sVT, 512,
                                          camE, 512LL * 512, 512, 512, 4096,
                                          0, nullptr, nullptr, 0, nullptr);
    cam_softmax<<<dim3(512, BATCH), 256>>>(camE, camA);
    // sc_feat[c][n] = gamma * sum_d attnT[d][c] * feat2[d][n] + feat2
    gemm_bf16<<<dim3(32, 4, BATCH), 256>>>(camA, 512LL * 512, 512, feat2, sF, 4096,
                                           sc, sF, 4096, 512, 512,
                                           2, nullptr, feat2, sF, cgamma);
    conv3x3_bf16<<<cgrid, 256>>>(sc, wt52H, wt52L, 512,
                                 bn52_s, bn52_b, bn52_m, bn52_v, saconv, fsum);

    // ---- final 1x1 conv ----
    gemm_bf16<<<dim3(32, 1, BATCH), 256>>>(w8T, 0, 19, fsum, sF, 4096,
                                           out, 19LL * 4096, 4096, 19, 512,
                                           1, b8, nullptr, 0, nullptr);
}

// round 8
// speedup vs baseline: 2.1970x; 1.2903x over previous
#include <cuda_runtime.h>
#include <cuda_bf16.h>
#include <stdint.h>
#include <math.h>

// ---------------------------------------------------------------------------
// DANet head — bf16 hi/lo 3-term tensor-core version, m16n8k16 MMA.
// R8: R7 + missing <stdint.h> fix. Conv inputs pre-split to hi/lo planes,
// 2-stage cp.async pipeline in conv.
// Shapes: B=4, Cin=2048, H=W=64 (N=4096 px/batch), Ci=512, Cq=64, Cout=19.
// ---------------------------------------------------------------------------

#define BATCH 4
#define NPIX  4096
#define COUT  512

// ------------------------- scratch (device globals) ------------------------
__device__ unsigned g_wt5a_hi[9u * 1024u * 512u];   // [tap][ci_pair][co]
__device__ unsigned g_wt5a_lo[9u * 1024u * 512u];
__device__ unsigned g_wt5c_hi[9u * 1024u * 512u];
__device__ unsigned g_wt5c_lo[9u * 1024u * 512u];
__device__ unsigned g_wt51_hi[9u * 256u * 512u];
__device__ unsigned g_wt51_lo[9u * 256u * 512u];
__device__ unsigned g_wt52_hi[9u * 256u * 512u];
__device__ unsigned g_wt52_lo[9u * 256u * 512u];
__device__ unsigned g_xsp_hi[(size_t)BATCH * 1024 * 4096];  // x split planes
__device__ unsigned g_xsp_lo[(size_t)BATCH * 1024 * 4096];
__device__ unsigned g_fsp_hi[(size_t)BATCH * 256 * 4096];   // sa/sc split (reused)
__device__ unsigned g_fsp_lo[(size_t)BATCH * 256 * 4096];
__device__ float g_wqT[512 * 64];
__device__ float g_wkT[512 * 64];
__device__ float g_wvT[512 * 512];
__device__ float g_w8T[512 * 19];
__device__ float g_feat1[(size_t)BATCH * 512 * 4096];
__device__ float g_feat2[(size_t)BATCH * 512 * 4096];
__device__ float g_q[(size_t)BATCH * 64 * 4096];
__device__ float g_k[(size_t)BATCH * 64 * 4096];
__device__ float g_vT[(size_t)BATCH * 4096 * 512];
__device__ float g_G[(size_t)BATCH * 4096 * 4096];
__device__ float g_sa[(size_t)BATCH * 512 * 4096];
__device__ float g_sc[(size_t)BATCH * 512 * 4096];
__device__ float g_saconv[(size_t)BATCH * 512 * 4096];
__device__ float g_fsum[(size_t)BATCH * 512 * 4096];
__device__ float g_fT[(size_t)BATCH * 4096 * 512];
__device__ float g_camE[(size_t)BATCH * 512 * 512];
__device__ float g_camA[(size_t)BATCH * 512 * 512];

// ------------------------- bf16 split helpers -------------------------------
__device__ __forceinline__ void split2(float x0, float x1,
                                       unsigned& hi, unsigned& lo)
{
    __nv_bfloat16 h0 = __float2bfloat16_rn(x0);
    __nv_bfloat16 h1 = __float2bfloat16_rn(x1);
    __nv_bfloat16 l0 = __float2bfloat16_rn(x0 - __bfloat162float(h0));
    __nv_bfloat16 l1 = __float2bfloat16_rn(x1 - __bfloat162float(h1));
    hi = (unsigned)__bfloat16_as_ushort(h0) | ((unsigned)__bfloat16_as_ushort(h1) << 16);
    lo = (unsigned)__bfloat16_as_ushort(l0) | ((unsigned)__bfloat16_as_ushort(l1) << 16);
}

__device__ __forceinline__ void mma_bf16(float* d, const unsigned* a, const unsigned* b) {
    asm volatile(
        "mma.sync.aligned.m16n8k16.row.col.f32.bf16.bf16.f32 "
        "{%0,%1,%2,%3}, {%4,%5,%6,%7}, {%8,%9}, {%0,%1,%2,%3};\n"
        : "+f"(d[0]), "+f"(d[1]), "+f"(d[2]), "+f"(d[3])
        : "r"(a[0]), "r"(a[1]), "r"(a[2]), "r"(a[3]), "r"(b[0]), "r"(b[1]));
}

#define CP_ASYNC16(dst, src) \
    asm volatile("cp.async.cg.shared.global [%0], [%1], 16;" :: "r"(dst), "l"(src))
#define CP_ASYNC4Z(dst, src, srcsz) \
    asm volatile("cp.async.ca.shared.global [%0], [%1], 4, %2;" :: "r"(dst), "l"(src), "r"(srcsz))
#define CP_COMMIT() asm volatile("cp.async.commit_group;" ::: "memory")

// ------------------------- weight re-layout ---------------------------------
__global__ void wtrans3x3(const float* __restrict__ W,
                          unsigned* __restrict__ Whi, unsigned* __restrict__ Wlo,
                          int Cin)
{
    int cp2 = Cin >> 1;
    long long n = (long long)512 * cp2 * 9;
    long long cs = (long long)cp2 * 512;
    for (long long i = (long long)blockIdx.x * blockDim.x + threadIdx.x; i < n;
         i += (long long)gridDim.x * blockDim.x) {
        int tap = (int)(i / cs);
        long long r = i - (long long)tap * cs;
        int cp = (int)(r / 512);
        int co = (int)(r - (long long)cp * 512);
        float w0 = W[((long long)co * Cin + 2 * cp) * 9 + tap];
        float w1 = W[((long long)co * Cin + 2 * cp + 1) * 9 + tap];
        unsigned hi, lo;
        split2(w0, w1, hi, lo);
        Whi[i] = hi;
        Wlo[i] = lo;
    }
}

__global__ void wtrans1x1(const float* __restrict__ W, float* __restrict__ Wt,
                          int Cin, int Cout)
{
    int i = blockIdx.x * blockDim.x + threadIdx.x;
    if (i < Cin * Cout) {
        int ci = i / Cout, co = i - ci * Cout;
        Wt[i] = W[co * Cin + ci];
    }
}

// ------------------------- feature split to hi/lo planes --------------------
// in: [BATCH][C][NPIX] f32 -> hi/lo: [BATCH][C/2][NPIX] packed u32
__global__ void splitplanes(const float* __restrict__ in,
                            unsigned* __restrict__ hi, unsigned* __restrict__ lo,
                            int C)
{
    int cp2 = C >> 1;
    long long total = (long long)BATCH * cp2 * NPIX;
    for (long long i = (long long)blockIdx.x * blockDim.x + threadIdx.x; i < total;
         i += (long long)gridDim.x * blockDim.x) {
        long long n = i & (NPIX - 1);
        long long t = i >> 12;             // / NPIX
        int cp = (int)(t % cp2);
        int b = (int)(t / cp2);
        const float* p = in + ((size_t)b * C + 2 * cp) * NPIX + n;
        unsigned h, l;
        split2(p[0], p[NPIX], h, l);
        hi[i] = h;
        lo[i] = l;
    }
}

// Padded row width for MMA-operand smem tiles (u32 words per k-row)
#define LDW 136
#define PL  (16 * LDW)          // one plane: 16 k-pair rows
#define STG (4 * PL)            // stage: AsHi, AsLo, BsHi, BsLo
#define CONV_SMEM_BYTES (2 * STG * 4)

// ------------------------- 3x3 conv (bf16x3 MMA, cp.async pipeline) --------
__global__ void __launch_bounds__(256, 1)
conv3x3_bf16(const unsigned* __restrict__ XHi, const unsigned* __restrict__ XLo,
             const unsigned* __restrict__ Whi, const unsigned* __restrict__ Wlo,
             int Cin,
             const float* __restrict__ bns, const float* __restrict__ bnb,
             const float* __restrict__ bnm, const float* __restrict__ bnv,
             const float* __restrict__ res, float* __restrict__ Y)
{
    extern __shared__ unsigned smemRaw[];
    unsigned sbase;
    asm("{ .reg .u64 t; cvta.to.shared.u64 t, %1; cvt.u32.u64 %0, t; }"
        : "=r"(sbase) : "l"(smemRaw));

    const int p0  = blockIdx.x * 128;
    const int co0 = blockIdx.y * 128;
    const int b   = blockIdx.z;
    const int cp2 = Cin >> 1;
    const int nch = Cin >> 5;              // chunks of 32 ci
    const int total = 9 * nch;

    const unsigned* XHb = XHi + (size_t)b * cp2 * NPIX;
    const unsigned* XLb = XLo + (size_t)b * cp2 * NPIX;

    const int tid  = threadIdx.x;
    const int lane = tid & 31;
    const int warp = tid >> 5;
    const int wm = warp >> 2;
    const int wn = warp & 3;
    const int e    = tid & 127;
    const int kprow = tid >> 7;

    float acc[4][4][4];
#pragma unroll
    for (int mi = 0; mi < 4; mi++)
#pragma unroll
        for (int ni = 0; ni < 4; ni++)
#pragma unroll
            for (int r = 0; r < 4; r++) acc[mi][ni][r] = 0.f;

    const int p  = p0 + e;
    const int py = p >> 6, px = p & 63;
    const int q    = lane & 3;
    const int r    = lane >> 2;
    const int mrow = wm * 64 + r;
    const int ncol = wn * 32 + r;

    // ---- prefetch one iteration into given stage ----
    auto prefetch = [&](int it, int stage) {
        int tap = it / nch;
        int cc  = it - tap * nch;
        int c0p = cc << 4;                 // ci-pair base (16 pairs per chunk)
        unsigned sb = sbase + (unsigned)(stage * STG) * 4u;

        // A (weights): 16B cp.async, 2 per plane per thread
        const unsigned* WH = Whi + (size_t)tap * cp2 * COUT + (size_t)c0p * COUT + co0;
        const unsigned* WL = Wlo + (size_t)tap * cp2 * COUT + (size_t)c0p * COUT + co0;
#pragma unroll
        for (int j = 0; j < 2; j++) {
            int idx = tid * 4 + j * 1024;
            int kp = idx >> 7, e4 = idx & 127;
            CP_ASYNC16(sb + (unsigned)(kp * LDW + e4) * 4u, WH + (size_t)kp * COUT + e4);
            CP_ASYNC16(sb + (unsigned)(PL + kp * LDW + e4) * 4u, WL + (size_t)kp * COUT + e4);
        }

        // B (pixels): 4B cp.async with zero-fill at borders
        int dy = tap / 3 - 1, dx = tap % 3 - 1;
        int yy = py + dy, xx = px + dx;
        bool ok = ((unsigned)yy < 64u) && ((unsigned)xx < 64u);
        int pofs = ok ? ((yy << 6) + xx) : 0;
        unsigned ssz = ok ? 4u : 0u;
        const unsigned* XH = XHb + (size_t)c0p * NPIX + pofs;
        const unsigned* XL = XLb + (size_t)c0p * NPIX + pofs;
#pragma unroll
        for (int s = 0; s < 8; s++) {
            int kp = kprow + 2 * s;
            CP_ASYNC4Z(sb + (unsigned)(2 * PL + kp * LDW + e) * 4u, XH + (size_t)kp * NPIX, ssz);
            CP_ASYNC4Z(sb + (unsigned)(3 * PL + kp * LDW + e) * 4u, XL + (size_t)kp * NPIX, ssz);
        }
        CP_COMMIT();
    };

    prefetch(0, 0);

    for (int it = 0; it < total; it++) {
        int stage = it & 1;
        if (it + 1 < total) {
            prefetch(it + 1, stage ^ 1);
            asm volatile("cp.async.wait_group 1;" ::: "memory");
        } else {
            asm volatile("cp.async.wait_group 0;" ::: "memory");
        }
        __syncthreads();

        const unsigned* base = smemRaw + stage * STG;
        const unsigned (*AsHi)[LDW] = (const unsigned (*)[LDW])(base);
        const unsigned (*AsLo)[LDW] = (const unsigned (*)[LDW])(base + PL);
        const unsigned (*BsHi)[LDW] = (const unsigned (*)[LDW])(base + 2 * PL);
        const unsigned (*BsLo)[LDW] = (const unsigned (*)[LDW])(base + 3 * PL);

#pragma unroll
        for (int sl = 0; sl < 2; sl++) {
            const int kb = sl * 8;
            unsigned ahi[4][4], alo[4][4];
#pragma unroll
            for (int mi = 0; mi < 4; mi++) {
                int m = mrow + mi * 16;
                ahi[mi][0] = AsHi[kb + q][m];
                ahi[mi][1] = AsHi[kb + q][m + 8];
                ahi[mi][2] = AsHi[kb + q + 4][m];
                ahi[mi][3] = AsHi[kb + q + 4][m + 8];
                alo[mi][0] = AsLo[kb + q][m];
                alo[mi][1] = AsLo[kb + q][m + 8];
                alo[mi][2] = AsLo[kb + q + 4][m];
                alo[mi][3] = AsLo[kb + q + 4][m + 8];
            }
#pragma unroll
            for (int ni = 0; ni < 4; ni++) {
                int n = ncol + ni * 8;
                unsigned bhi[2], blo[2];
                bhi[0] = BsHi[kb + q][n];
                bhi[1] = BsHi[kb + q + 4][n];
                blo[0] = BsLo[kb + q][n];
                blo[1] = BsLo[kb + q + 4][n];
#pragma unroll
                for (int mi = 0; mi < 4; mi++) {
                    mma_bf16(acc[mi][ni], ahi[mi], bhi);
                    mma_bf16(acc[mi][ni], ahi[mi], blo);
                    mma_bf16(acc[mi][ni], alo[mi], bhi);
                }
            }
        }
        __syncthreads();
    }

    // epilogue: BN + ReLU (+ residual)
#pragma unroll
    for (int mi = 0; mi < 4; mi++) {
        int r0 = co0 + wm * 64 + mi * 16 + r;
        int r1 = r0 + 8;
        float sc0 = bns[r0] * rsqrtf(bnv[r0] + 1e-5f);
        float sh0 = bnb[r0] - sc0 * bnm[r0];
        float sc1 = bns[r1] * rsqrtf(bnv[r1] + 1e-5f);
        float sh1 = bnb[r1] - sc1 * bnm[r1];
#pragma unroll
        for (int ni = 0; ni < 4; ni++) {
            int c = p0 + wn * 32 + ni * 8 + 2 * q;
            size_t o0 = ((size_t)b * COUT + r0) * NPIX + c;
            size_t o1 = ((size_t)b * COUT + r1) * NPIX + c;
            float v00 = fmaxf(fmaf(sc0, acc[mi][ni][0], sh0), 0.f);
            float v01 = fmaxf(fmaf(sc0, acc[mi][ni][1], sh0), 0.f);
            float v10 = fmaxf(fmaf(sc1, acc[mi][ni][2], sh1), 0.f);
            float v11 = fmaxf(fmaf(sc1, acc[mi][ni][3], sh1), 0.f);
            if (res) {
                v00 += res[o0]; v01 += res[o0 + 1];
                v10 += res[o1]; v11 += res[o1 + 1];
            }
            *(float2*)&Y[o0] = make_float2(v00, v01);
            *(float2*)&Y[o1] = make_float2(v10, v11);
        }
    }
}

// ------------------------- generic TN GEMM (bf16x3 MMA) ----------------------
// C[i,j] = sum_k A[k*lda+i] * B[k*ldb+j]  (per blockIdx.z batch, strides s*)
// epi: 0 store | 1 +bias[i] | 2 gamma*acc + res[i*ldc+j] | 4 +bias[j]
__global__ void __launch_bounds__(256, 1)
gemm_bf16(const float* __restrict__ A, long long sA, int lda,
          const float* __restrict__ B, long long sB, int ldb,
          float* __restrict__ C, long long sC, int ldc,
          int M, int K, int epi,
          const float* __restrict__ bias,
          const float* __restrict__ res, long long sRes,
          const float* __restrict__ gammaPtr)
{
    __shared__ unsigned AsHi[16][LDW], AsLo[16][LDW];
    __shared__ unsigned BsHi[16][LDW], BsLo[16][LDW];

    const int bj = blockIdx.x * 128;
    const int bi = blockIdx.y * 128;
    const int z = blockIdx.z;
    A += (long long)z * sA;
    B += (long long)z * sB;
    C += (long long)z * sC;

    const int tid  = threadIdx.x;
    const int lane = tid & 31;
    const int warp = tid >> 5;
    const int wm = warp >> 2, wn = warp & 3;
    const int e    = tid & 127;
    const int kprow = tid >> 7;

    float acc[4][4][4];
#pragma unroll
    for (int mi = 0; mi < 4; mi++)
#pragma unroll
        for (int ni = 0; ni < 4; ni++)
#pragma unroll
            for (int rr = 0; rr < 4; rr++) acc[mi][ni][rr] = 0.f;

    const bool aok = (bi + e) < M;
    const int q    = lane & 3;
    const int r    = lane >> 2;
    const int mrow = wm * 64 + r;
    const int ncol = wn * 32 + r;

    for (int k0 = 0; k0 < K; k0 += 32) {
#pragma unroll
        for (int s = 0; s < 8; s++) {
            int kp = kprow + 2 * s;
            float a0 = aok ? A[(long long)(k0 + 2 * kp) * lda + bi + e] : 0.f;
            float a1 = aok ? A[(long long)(k0 + 2 * kp + 1) * lda + bi + e] : 0.f;
            unsigned hi, lo;
            split2(a0, a1, hi, lo);
            AsHi[kp][e] = hi; AsLo[kp][e] = lo;
            float b0 = B[(long long)(k0 + 2 * kp) * ldb + bj + e];
            float b1 = B[(long long)(k0 + 2 * kp + 1) * ldb + bj + e];
            split2(b0, b1, hi, lo);
            BsHi[kp][e] = hi; BsLo[kp][e] = lo;
        }
        __syncthreads();
#pragma unroll
        for (int sl = 0; sl < 2; sl++) {
            const int kb = sl * 8;
            unsigned ahi[4][4], alo[4][4];
#pragma unroll
            for (int mi = 0; mi < 4; mi++) {
                int m = mrow + mi * 16;
                ahi[mi][0] = AsHi[kb + q][m];
                ahi[mi][1] = AsHi[kb + q][m + 8];
                ahi[mi][2] = AsHi[kb + q + 4][m];
                ahi[mi][3] = AsHi[kb + q + 4][m + 8];
                alo[mi][0] = AsLo[kb + q][m];
                alo[mi][1] = AsLo[kb + q][m + 8];
                alo[mi][2] = AsLo[kb + q + 4][m];
                alo[mi][3] = AsLo[kb + q + 4][m + 8];
            }
#pragma unroll
            for (int ni = 0; ni < 4; ni++) {
                int n = ncol + ni * 8;
                unsigned bhi[2], blo[2];
                bhi[0] = BsHi[kb + q][n];
                bhi[1] = BsHi[kb + q + 4][n];
                blo[0] = BsLo[kb + q][n];
                blo[1] = BsLo[kb + q + 4][n];
#pragma unroll
                for (int mi = 0; mi < 4; mi++) {
                    mma_bf16(acc[mi][ni], ahi[mi], bhi);
                    mma_bf16(acc[mi][ni], ahi[mi], blo);
                    mma_bf16(acc[mi][ni], alo[mi], bhi);
                }
            }
        }
        __syncthreads();
    }

    const float gamma = (epi == 2) ? *gammaPtr : 1.f;
    const float* rz = (epi == 2) ? (res + (long long)z * sRes) : nullptr;

#pragma unroll
    for (int mi = 0; mi < 4; mi++) {
        int r0 = bi + wm * 64 + mi * 16 + r;
        int r1 = r0 + 8;
#pragma unroll
        for (int ni = 0; ni < 4; ni++) {
            int c = bj + wn * 32 + ni * 8 + 2 * q;
#pragma unroll
            for (int h = 0; h < 2; h++) {
                int rr = h ? r1 : r0;
                if (rr >= M) continue;
                float v0 = acc[mi][ni][h * 2 + 0];
                float v1 = acc[mi][ni][h * 2 + 1];
                long long o = (long long)rr * ldc + c;
                if (epi == 1) {
                    v0 += bias[rr]; v1 += bias[rr];
                } else if (epi == 2) {
                    v0 = fmaf(gamma, v0, rz[o]);
                    v1 = fmaf(gamma, v1, rz[o + 1]);
                } else if (epi == 4) {
                    v0 += bias[c]; v1 += bias[c + 1];
                }
                *(float2*)&C[o] = make_float2(v0, v1);
            }
        }
    }
}

// ------------------------- PAM row softmax (rows of 4096, in-place) --------
__global__ void softmax_rows4096(float* __restrict__ G)
{
    long long row = blockIdx.x;
    float* r = G + row * 4096;
    int t = threadIdx.x;

    float4 v[4];
    float mx = -INFINITY;
#pragma unroll
    for (int s = 0; s < 4; s++) {
        v[s] = ((const float4*)r)[t + s * 256];
        mx = fmaxf(mx, fmaxf(fmaxf(v[s].x, v[s].y), fmaxf(v[s].z, v[s].w)));
    }
    __shared__ float red[256];
    red[t] = mx; __syncthreads();
    for (int o = 128; o > 0; o >>= 1) {
        if (t < o) red[t] = fmaxf(red[t], red[t + o]);
        __syncthreads();
    }
    mx = red[0]; __syncthreads();

    float sum = 0.f;
#pragma unroll
    for (int s = 0; s < 4; s++) {
        v[s].x = __expf(v[s].x - mx);
        v[s].y = __expf(v[s].y - mx);
        v[s].z = __expf(v[s].z - mx);
        v[s].w = __expf(v[s].w - mx);
        sum += v[s].x + v[s].y + v[s].z + v[s].w;
    }
    red[t] = sum; __syncthreads();
    for (int o = 128; o > 0; o >>= 1) {
        if (t < o) red[t] += red[t + o];
        __syncthreads();
    }
    float inv = 1.f / red[0];
#pragma unroll
    for (int s = 0; s < 4; s++) {
        v[s].x *= inv; v[s].y *= inv; v[s].z *= inv; v[s].w *= inv;
        ((float4*)r)[t + s * 256] = v[s];
    }
}

// ------------------------- CAM softmax -------------------------------------
__global__ void cam_softmax(const float* __restrict__ E, float* __restrict__ AT)
{
    int c = blockIdx.x, b = blockIdx.y;
    const float* row = E + ((long long)b * 512 + c) * 512;
    float* outb = AT + (long long)b * 512 * 512;
    int t = threadIdx.x;

    float e0 = row[t], e1 = row[t + 256];
    __shared__ float red[256];

    red[t] = fmaxf(e0, e1); __syncthreads();
    for (int o = 128; o > 0; o >>= 1) {
        if (t < o) red[t] = fmaxf(red[t], red[t + o]);
        __syncthreads();
    }
    float rowmax = red[0]; __syncthreads();

    float t0 = rowmax - e0, t1 = rowmax - e1;
    red[t] = fmaxf(t0, t1); __syncthreads();
    for (int o = 128; o > 0; o >>= 1) {
        if (t < o) red[t] = fmaxf(red[t], red[t + o]);
        __syncthreads();
    }
    float m2 = red[0]; __syncthreads();

    float x0 = __expf(t0 - m2), x1 = __expf(t1 - m2);
    red[t] = x0 + x1; __syncthreads();
    for (int o = 128; o > 0; o >>= 1) {
        if (t < o) red[t] += red[t + o];
        __syncthreads();
    }
    float inv = 1.f / red[0];
    outb[(long long)t * 512 + c] = x0 * inv;
    outb[(long long)(t + 256) * 512 + c] = x1 * inv;
}

// ------------------------- transpose [512,4096] -> [4096,512] per batch ----
__global__ void transpose_cn(const float* __restrict__ in, float* __restrict__ out)
{
    __shared__ float tile[32][33];
    int b = blockIdx.z;
    int n0 = blockIdx.x * 32, c0 = blockIdx.y * 32;
    const float* ib = in + (long long)b * 512 * 4096;
    float* ob = out + (long long)b * 4096 * 512;
    int tx = threadIdx.x, ty = threadIdx.y;
#pragma unroll
    for (int s = 0; s < 32; s += 8)
        tile[ty + s][tx] = ib[(long long)(c0 + ty + s) * 4096 + n0 + tx];
    __syncthreads();
#pragma unroll
    for (int s = 0; s < 32; s += 8)
        ob[(long long)(n0 + ty + s) * 512 + c0 + tx] = tile[tx][ty + s];
}

// ---------------------------------------------------------------------------
extern "C" void kernel_launch(void* const* d_in, const int* in_sizes, int n_in,
                              void* d_out, int out_size)
{
    (void)in_sizes; (void)n_in; (void)out_size;
    const float* x      = (const float*)d_in[0];
    const float* w5a    = (const float*)d_in[1];
    const float* bn5a_s = (const float*)d_in[2];
    const float* bn5a_b = (const float*)d_in[3];
    const float* bn5a_m = (const float*)d_in[4];
    const float* bn5a_v = (const float*)d_in[5];
    const float* w5c    = (const float*)d_in[6];
    const float* bn5c_s = (const float*)d_in[7];
    const float* bn5c_b = (const float*)d_in[8];
    const float* bn5c_m = (const float*)d_in[9];
    const float* bn5c_v = (const float*)d_in[10];
    const float* wq     = (const float*)d_in[11];
    const float* qb     = (const float*)d_in[12];
    const float* wk     = (const float*)d_in[13];
    const float* kb     = (const float*)d_in[14];
    const float* wv     = (const float*)d_in[15];
    const float* vb     = (const float*)d_in[16];
    const float* pgamma = (const float*)d_in[17];
    const float* cgamma = (const float*)d_in[18];
    const float* w51    = (const float*)d_in[19];
    const float* bn51_s = (const float*)d_in[20];
    const float* bn51_b = (const float*)d_in[21];
    const float* bn51_m = (const float*)d_in[22];
    const float* bn51_v = (const float*)d_in[23];
    const float* w52    = (const float*)d_in[24];
    const float* bn52_s = (const float*)d_in[25];
    const float* bn52_b = (const float*)d_in[26];
    const float* bn52_m = (const float*)d_in[27];
    const float* bn52_v = (const float*)d_in[28];
    const float* w8     = (const float*)d_in[29];
    const float* b8     = (const float*)d_in[30];
    float* out = (float*)d_out;

    unsigned *wt5aH, *wt5aL, *wt5cH, *wt5cL, *wt51H, *wt51L, *wt52H, *wt52L;
    unsigned *xspH, *xspL, *fspH, *fspL;
    float *wqT, *wkT, *wvT, *w8T;
    float *feat1, *feat2, *q, *k, *vT, *G, *sa, *sc, *saconv, *fsum, *fT, *camE, *camA;
    cudaGetSymbolAddress((void**)&wt5aH, g_wt5a_hi);
    cudaGetSymbolAddress((void**)&wt5aL, g_wt5a_lo);
    cudaGetSymbolAddress((void**)&wt5cH, g_wt5c_hi);
    cudaGetSymbolAddress((void**)&wt5cL, g_wt5c_lo);
    cudaGetSymbolAddress((void**)&wt51H, g_wt51_hi);
    cudaGetSymbolAddress((void**)&wt51L, g_wt51_lo);
    cudaGetSymbolAddress((void**)&wt52H, g_wt52_hi);
    cudaGetSymbolAddress((void**)&wt52L, g_wt52_lo);
    cudaGetSymbolAddress((void**)&xspH, g_xsp_hi);
    cudaGetSymbolAddress((void**)&xspL, g_xsp_lo);
    cudaGetSymbolAddress((void**)&fspH, g_fsp_hi);
    cudaGetSymbolAddress((void**)&fspL, g_fsp_lo);
    cudaGetSymbolAddress((void**)&wqT, g_wqT);
    cudaGetSymbolAddress((void**)&wkT, g_wkT);
    cudaGetSymbolAddress((void**)&wvT, g_wvT);
    cudaGetSymbolAddress((void**)&w8T, g_w8T);
    cudaGetSymbolAddress((void**)&feat1, g_feat1);
    cudaGetSymbolAddress((void**)&feat2, g_feat2);
    cudaGetSymbolAddress((void**)&q, g_q);
    cudaGetSymbolAddress((void**)&k, g_k);
    cudaGetSymbolAddress((void**)&vT, g_vT);
    cudaGetSymbolAddress((void**)&G, g_G);
    cudaGetSymbolAddress((void**)&sa, g_sa);
    cudaGetSymbolAddress((void**)&sc, g_sc);
    cudaGetSymbolAddress((void**)&saconv, g_saconv);
    cudaGetSymbolAddress((void**)&fsum, g_fsum);
    cudaGetSymbolAddress((void**)&fT, g_fT);
    cudaGetSymbolAddress((void**)&camE, g_camE);
    cudaGetSymbolAddress((void**)&camA, g_camA);

    static bool attrSet = false;
    if (!attrSet) {
        cudaFuncSetAttribute(conv3x3_bf16,
                             cudaFuncAttributeMaxDynamicSharedMemorySize,
                             CONV_SMEM_BYTES);
        attrSet = true;
    }

    // ---- weight re-layout + input split ----
    wtrans3x3<<<4096, 256>>>(w5a, wt5aH, wt5aL, 2048);
    wtrans3x3<<<4096, 256>>>(w5c, wt5cH, wt5cL, 2048);
    wtrans3x3<<<4096, 256>>>(w51, wt51H, wt51L, 512);
    wtrans3x3<<<4096, 256>>>(w52, wt52H, wt52L, 512);
    wtrans1x1<<<(512 * 64 + 255) / 256, 256>>>(wq, wqT, 512, 64);
    wtrans1x1<<<(512 * 64 + 255) / 256, 256>>>(wk, wkT, 512, 64);
    wtrans1x1<<<(512 * 512 + 255) / 256, 256>>>(wv, wvT, 512, 512);
    wtrans1x1<<<(512 * 19 + 255) / 256, 256>>>(w8, w8T, 512, 19);
    splitplanes<<<8192, 256>>>(x, xspH, xspL, 2048);

    const dim3 cgrid(32, 4, BATCH);

    // ---- stem convs ----
    conv3x3_bf16<<<cgrid, 256, CONV_SMEM_BYTES>>>(
        xspH, xspL, wt5aH, wt5aL, 2048,
        bn5a_s, bn5a_b, bn5a_m, bn5a_v, nullptr, feat1);
    conv3x3_bf16<<<cgrid, 256, CONV_SMEM_BYTES>>>(
        xspH, xspL, wt5cH, wt5cL, 2048,
        bn5c_s, bn5c_b, bn5c_m, bn5c_v, nullptr, feat2);

    const long long sF = 512LL * 4096;
    const long long sQ = 64LL * 4096;
    const long long sVT = 4096LL * 512;
    const long long sG = 4096LL * 4096;

    // ---- PAM ----
    gemm_bf16<<<dim3(32, 1, BATCH), 256>>>(wqT, 0, 64, feat1, sF, 4096,
                                           q, sQ, 4096, 64, 512,
                                           1, qb, nullptr, 0, nullptr);
    gemm_bf16<<<dim3(32, 1, BATCH), 256>>>(wkT, 0, 64, feat1, sF, 4096,
                                           k, sQ, 4096, 64, 512,
                                           1, kb, nullptr, 0, nullptr);
    gemm_bf16<<<dim3(4, 32, BATCH), 256>>>(feat1, sF, 4096, wvT, 0, 512,
                                           vT, sVT, 512, 4096, 512,
                                           4, vb, nullptr, 0, nullptr);
    gemm_bf16<<<dim3(32, 32, BATCH), 256>>>(k, sQ, 4096, q, sQ, 4096,
                                            G, sG, 4096, 4096, 64,
                                            0, nullptr, nullptr, 0, nullptr);
    softmax_rows4096<<<BATCH * 4096, 256>>>(G);
    gemm_bf16<<<dim3(32, 4, BATCH), 256>>>(vT, sVT, 512, G, sG, 4096,
                                           sa, sF, 4096, 512, 4096,
                                           2, nullptr, feat1, sF, pgamma);
    splitplanes<<<4096, 256>>>(sa, fspH, fspL, 512);
    conv3x3_bf16<<<cgrid, 256, CONV_SMEM_BYTES>>>(
        fspH, fspL, wt51H, wt51L, 512,
        bn51_s, bn51_b, bn51_m, bn51_v, nullptr, saconv);

    // ---- CAM ----
    transpose_cn<<<dim3(128, 16, BATCH), dim3(32, 8)>>>(feat2, fT);
    gemm_bf16<<<dim3(4, 4, BATCH), 256>>>(fT, sVT, 512, fT, sVT, 512,
                                          camE, 512LL * 512, 512, 512, 4096,
                                          0, nullptr, nullptr, 0, nullptr);
    cam_softmax<<<dim3(512, BATCH), 256>>>(camE, camA);
    gemm_bf16<<<dim3(32, 4, BATCH), 256>>>(camA, 512LL * 512, 512, feat2, sF, 4096,
                                           sc, sF, 4096, 512, 512,
                                           2, nullptr, feat2, sF, cgamma);
    splitplanes<<<4096, 256>>>(sc, fspH, fspL, 512);
    conv3x3_bf16<<<cgrid, 256, CONV_SMEM_BYTES>>>(
        fspH, fspL, wt52H, wt52L, 512,
        bn52_s, bn52_b, bn52_m, bn52_v, saconv, fsum);

    // ---- final 1x1 conv ----
    gemm_bf16<<<dim3(32, 1, BATCH), 256>>>(w8T, 0, 19, fsum, sF, 4096,
                                           out, 19LL * 4096, 4096, 19, 512,
                                           1, b8, nullptr, 0, nullptr);
}